// round 3
// baseline (speedup 1.0000x reference)
#include <cuda_runtime.h>
#include <math.h>
#include <stdint.h>

// Problem constants (shapes fixed by the dataset)
#define B_    4
#define S0    12
#define T_    24          // template side (2*s0)
#define S_    576         // T_*T_
#define DIM   256
#define NP    128         // nPnt
#define HID   512         // 4*nPnt
#define S2    48          // new2 = 2*new_size
#define H_    120
#define W_    160

typedef unsigned long long ull;

// ---------------- scratch (device globals; no allocation allowed) -------------
__device__ float g_t   [B_ * S_ * DIM];        // template tokens [4,576,256]
__device__ float g_A0  [B_ * S_ * NP];         // t @ P^T / 16
__device__ float g_H   [B_ * S_ * 2 * HID];    // hidden, nr cols [0,512), na [512,1024)
__device__ float g_adj [B_ * S_ * NP];         // node_adj after nr MLP
__device__ float g_attn[B_ * S_ * NP];         // na MLP out, softmax in-place
__device__ float g_tokn[(long)B_ * S2 * NP * DIM];  // token_n [4,48,128,256]
__device__ float g_fus [B_ * NP * DIM];        // token_fused [4,128,256]
__device__ float g_U   [B_ * S_ * DIM];        // unique output rows

__device__ __forceinline__ float gelu_exact(float x) {
    return 0.5f * x * (1.0f + erff(x * 0.70710678118654752440f));
}

__device__ __forceinline__ float tf32_hi(float x) {
    uint32_t u; asm("cvt.rna.tf32.f32 %0, %1;" : "=r"(u) : "f"(x));
    return __uint_as_float(u);
}

__device__ __forceinline__ ull pack2(float x, float y) {
    ull r; asm("mov.b64 %0, {%1, %2};" : "=l"(r) : "f"(x), "f"(y)); return r;
}
__device__ __forceinline__ void unpack2(ull v, float& x, float& y) {
    asm("mov.b64 {%0, %1}, %2;" : "=f"(x), "=f"(y) : "l"(v));
}
__device__ __forceinline__ ull fma2(ull a, ull b, ull c) {
    ull d; asm("fma.rn.f32x2 %0, %1, %2, %3;" : "=l"(d) : "l"(a), "l"(b), "l"(c));
    return d;
}

__device__ __forceinline__ void mma8(float d[4], const uint32_t a[4], const uint32_t b[2]) {
    asm volatile("mma.sync.aligned.m16n8k8.row.col.f32.tf32.tf32.f32 "
                 "{%0,%1,%2,%3},{%4,%5,%6,%7},{%8,%9},{%0,%1,%2,%3};\n"
                 : "+f"(d[0]), "+f"(d[1]), "+f"(d[2]), "+f"(d[3])
                 : "r"(a[0]), "r"(a[1]), "r"(a[2]), "r"(a[3]), "r"(b[0]), "r"(b[1]));
}

// ---------------- kernel 1: build template t (repeat_interleave x2) -----------
__global__ void build_t_kernel(const float* __restrict__ token_init) {
    int s = blockIdx.x;            // 0..575
    int b = blockIdx.y;
    int hh = s / T_, ww = s % T_;
    int d = threadIdx.x;           // 256
    g_t[(b * S_ + s) * DIM + d] =
        token_init[((b * S0 + (hh >> 1)) * S0 + (ww >> 1)) * DIM + d];
}

// ===================== tf32 tensor-core GEMM, 3xTF32 split ====================
// 64x64 tile, BK=16, 256 threads (8 warps, each 32x16), m16n8k8 mma.
// C = act( alpha * A @ B(^T) + bias ) + R. Split: D = AhBh + AhBl + AlBh.
#define BM 64
#define BN 64
#define BK 16

template<bool TRANSB, bool ACT, bool BIAS, bool RESID, bool DUAL>
__global__ __launch_bounds__(256)
void gemm_tc(const float* __restrict__ A,
             const float* __restrict__ B0, const float* __restrict__ B1,
             const float* __restrict__ bias0, const float* __restrict__ bias1,
             const float* __restrict__ R,
             float* __restrict__ C0, float* __restrict__ C1,
             int K, float alpha,
             long sA, int lda, int ofsA,
             long sB, int ldb,
             long sC, int ldc, int ofsC,
             long sR)
{
    const int z  = blockIdx.z;
    const int b  = DUAL ? (z >> 1) : z;
    const int br = DUAL ? (z & 1) : 0;

    const float* Bw  = (DUAL && br) ? B1 : B0;
    const float* bia = (DUAL && br) ? bias1 : bias0;
    float*       C   = (DUAL && br) ? C1 : C0;

    A  += (long)b * sA + (long)br * ofsA;
    Bw += (long)b * sB;
    C  += (long)b * sC + (long)br * ofsC;
    const float* Rp = RESID ? (R + (long)b * sR) : nullptr;

    __shared__ float Ah[BK][BM + 4], Al[BK][BM + 4];
    __shared__ float Bh[BK][BN + 4], Bl[BK][BN + 4];

    const int tid  = threadIdx.x;
    const int lane = tid & 31;
    const int warp = tid >> 5;
    const int g    = lane >> 2;     // group id 0..7
    const int tg   = lane & 3;      // thread in group
    const int wm   = warp >> 2;     // 0..1
    const int wn   = warp & 3;      // 0..3
    const int m0w  = wm * 32;
    const int n0w  = wn * 16;
    const int row0 = blockIdx.y * BM;
    const int col0 = blockIdx.x * BN;

    // load indices
    const int arow = tid >> 2;            // 0..63
    const int acol = (tid & 3) * 4;       // 0,4,8,12
    const int bk   = tid >> 4;            // 0..15 (no-trans)
    const int bn4  = (tid & 15) * 4;      // 0..60

    float d[2][2][4];
#pragma unroll
    for (int i = 0; i < 2; i++)
#pragma unroll
        for (int j = 0; j < 2; j++)
#pragma unroll
            for (int q = 0; q < 4; q++) d[i][j][q] = 0.f;

    const int kT = K / BK;
    float4 aR, bR;
    aR = *(const float4*)&A[(long)(row0 + arow) * lda + acol];
    if (TRANSB)
        bR = *(const float4*)&Bw[(long)(col0 + arow) * ldb + acol];
    else
        bR = *(const float4*)&Bw[(long)bk * ldb + col0 + bn4];

    for (int t = 0; t < kT; t++) {
        // split + store to smem
        {
            float ax[4] = {aR.x, aR.y, aR.z, aR.w};
#pragma unroll
            for (int j = 0; j < 4; j++) {
                float hi = tf32_hi(ax[j]);
                Ah[acol + j][arow] = hi;
                Al[acol + j][arow] = ax[j] - hi;
            }
            float bx[4] = {bR.x, bR.y, bR.z, bR.w};
            if (TRANSB) {
#pragma unroll
                for (int j = 0; j < 4; j++) {
                    float hi = tf32_hi(bx[j]);
                    Bh[acol + j][arow] = hi;
                    Bl[acol + j][arow] = bx[j] - hi;
                }
            } else {
#pragma unroll
                for (int j = 0; j < 4; j++) {
                    float hi = tf32_hi(bx[j]);
                    Bh[bk][bn4 + j] = hi;
                    Bl[bk][bn4 + j] = bx[j] - hi;
                }
            }
        }
        __syncthreads();

        if (t + 1 < kT) {
            const int k0 = (t + 1) * BK;
            aR = *(const float4*)&A[(long)(row0 + arow) * lda + k0 + acol];
            if (TRANSB)
                bR = *(const float4*)&Bw[(long)(col0 + arow) * ldb + k0 + acol];
            else
                bR = *(const float4*)&Bw[(long)(k0 + bk) * ldb + col0 + bn4];
        }

#pragma unroll
        for (int kk = 0; kk < BK; kk += 8) {
            uint32_t ah[2][4], al[2][4], bh[2][2], bl[2][2];
#pragma unroll
            for (int mt = 0; mt < 2; mt++) {
                const int m = m0w + mt * 16 + g;
                ah[mt][0] = __float_as_uint(Ah[kk + tg][m]);
                ah[mt][1] = __float_as_uint(Ah[kk + tg][m + 8]);
                ah[mt][2] = __float_as_uint(Ah[kk + tg + 4][m]);
                ah[mt][3] = __float_as_uint(Ah[kk + tg + 4][m + 8]);
                al[mt][0] = __float_as_uint(Al[kk + tg][m]);
                al[mt][1] = __float_as_uint(Al[kk + tg][m + 8]);
                al[mt][2] = __float_as_uint(Al[kk + tg + 4][m]);
                al[mt][3] = __float_as_uint(Al[kk + tg + 4][m + 8]);
            }
#pragma unroll
            for (int nt = 0; nt < 2; nt++) {
                const int n = n0w + nt * 8 + g;
                bh[nt][0] = __float_as_uint(Bh[kk + tg][n]);
                bh[nt][1] = __float_as_uint(Bh[kk + tg + 4][n]);
                bl[nt][0] = __float_as_uint(Bl[kk + tg][n]);
                bl[nt][1] = __float_as_uint(Bl[kk + tg + 4][n]);
            }
#pragma unroll
            for (int mt = 0; mt < 2; mt++)
#pragma unroll
                for (int nt = 0; nt < 2; nt++) {
                    mma8(d[mt][nt], ah[mt], bh[nt]);
                    mma8(d[mt][nt], ah[mt], bl[nt]);
                    mma8(d[mt][nt], al[mt], bh[nt]);
                }
        }
        __syncthreads();
    }

    // epilogue: c0/c1 -> (row, col..col+1), c2/c3 -> (row+8, ...)
#pragma unroll
    for (int mt = 0; mt < 2; mt++) {
#pragma unroll
        for (int nt = 0; nt < 2; nt++) {
            const int row = row0 + m0w + mt * 16 + g;
            const int col = col0 + n0w + nt * 8 + tg * 2;
            float b0 = 0.f, b1 = 0.f;
            if (BIAS) { b0 = bia[col]; b1 = bia[col + 1]; }
#pragma unroll
            for (int h = 0; h < 2; h++) {
                const int r = row + h * 8;
                float v0 = d[mt][nt][2 * h + 0] * alpha + b0;
                float v1 = d[mt][nt][2 * h + 1] * alpha + b1;
                if (ACT) { v0 = gelu_exact(v0); v1 = gelu_exact(v1); }
                if (RESID) {
                    const float2 rr = *(const float2*)&Rp[(long)r * ldc + col];
                    v0 += rr.x; v1 += rr.y;
                }
                *(float2*)&C[(long)r * ldc + col] = make_float2(v0, v1);
            }
        }
    }
}

// ---------------- node_w / node_h: contract over 24 along w (or h) ------------
__global__ __launch_bounds__(256)
void node_wh_kernel(float rs) {
    __shared__ __align__(16) float adj_s[T_][NP];     // 12 KB
    __shared__ __align__(16) float t_s  [T_][DIM];    // 24 KB
    const int fix  = blockIdx.x;
    const int b    = blockIdx.y;
    const int mode = blockIdx.z;
    const int tid  = threadIdx.x;

    for (int idx = tid; idx < T_ * NP; idx += 256) {
        int m = idx >> 7, p = idx & 127;
        int h = mode ? m : fix;
        int w = mode ? fix : m;
        adj_s[m][p] = g_adj[((b * S_) + h * T_ + w) * NP + p];
    }
    for (int idx = tid; idx < T_ * DIM; idx += 256) {
        int m = idx >> 8, d = idx & 255;
        int h = mode ? m : fix;
        int w = mode ? fix : m;
        t_s[m][d] = g_t[((b * S_) + h * T_ + w) * DIM + d];
    }
    __syncthreads();

    const int d = tid;
    const int srow = mode ? (T_ + fix) : fix;
#pragma unroll
    for (int pb = 0; pb < 8; pb++) {
        ull acc2[8];
#pragma unroll
        for (int i = 0; i < 8; i++) acc2[i] = pack2(0.f, 0.f);
        for (int m = 0; m < T_; m++) {
            float tv = t_s[m][d];
            ull tv2 = pack2(tv, tv);
            const ull* ap = (const ull*)&adj_s[m][pb * 16];
#pragma unroll
            for (int i = 0; i < 8; i++)
                acc2[i] = fma2(ap[i], tv2, acc2[i]);
        }
#pragma unroll
        for (int i = 0; i < 8; i++) {
            float x, y; unpack2(acc2[i], x, y);
            g_tokn[((long)(b * S2 + srow) * NP + pb * 16 + 2 * i + 0) * DIM + d] = x * rs;
            g_tokn[((long)(b * S2 + srow) * NP + pb * 16 + 2 * i + 1) * DIM + d] = y * rs;
        }
    }
}

// ---------------- token_fused MLP over the 48-axis (2 d's per thread) ---------
__global__ __launch_bounds__(128)
void token_fused_kernel(const float* __restrict__ w1, const float* __restrict__ b1,
                        const float* __restrict__ w2, const float* __restrict__ b2) {
    __shared__ float w1t[S2][S2];   // transposed: w1t[j][s] = w1[s][j]
    __shared__ float b1s[S2];
    __shared__ float w2s[S2];
    const int tid = threadIdx.x;
    for (int idx = tid; idx < S2 * S2; idx += 128) {
        int s = idx / S2, j = idx % S2;
        w1t[j][s] = w1[idx];
    }
    if (tid < S2) { b1s[tid] = b1[tid]; w2s[tid] = w2[tid]; }
    __syncthreads();

    const int bp = blockIdx.x;        // 0..511 = b*128+p
    const int b  = bp >> 7;
    const int p  = bp & 127;
    const int d  = tid * 2;

    float xa[S2], xb[S2];
#pragma unroll
    for (int s = 0; s < S2; s++) {
        float2 v = *(const float2*)&g_tokn[((long)(b * S2 + s) * NP + p) * DIM + d];
        xa[s] = v.x; xb[s] = v.y;
    }

    float outa = b2[0], outb = b2[0];
    for (int j = 0; j < S2; j++) {
        float a0 = b1s[j], a1 = b1s[j];
        const float4* wr = (const float4*)&w1t[j][0];
#pragma unroll
        for (int s4 = 0; s4 < S2 / 4; s4++) {
            float4 wv = wr[s4];
            a0 += xa[s4 * 4 + 0] * wv.x + xa[s4 * 4 + 1] * wv.y
                + xa[s4 * 4 + 2] * wv.z + xa[s4 * 4 + 3] * wv.w;
            a1 += xb[s4 * 4 + 0] * wv.x + xb[s4 * 4 + 1] * wv.y
                + xb[s4 * 4 + 2] * wv.z + xb[s4 * 4 + 3] * wv.w;
        }
        float w2v = w2s[j];
        outa += gelu_exact(a0) * w2v;
        outb += gelu_exact(a1) * w2v;
    }
    *(float2*)&g_fus[bp * DIM + d] = make_float2(outa, outb);
}

// ---------------- row softmax, N = 128, one block per row ---------------------
__global__ __launch_bounds__(128)
void softmax128_kernel(float* __restrict__ X) {
    const int row = blockIdx.x;
    const int t = threadIdx.x;
    float v = X[row * NP + t];
    __shared__ float red[4];
    float m = v;
#pragma unroll
    for (int o = 16; o; o >>= 1) m = fmaxf(m, __shfl_xor_sync(0xffffffffu, m, o));
    if ((t & 31) == 0) red[t >> 5] = m;
    __syncthreads();
    m = fmaxf(fmaxf(red[0], red[1]), fmaxf(red[2], red[3]));
    float e = expf(v - m);
    __syncthreads();
    float s = e;
#pragma unroll
    for (int o = 16; o; o >>= 1) s += __shfl_xor_sync(0xffffffffu, s, o);
    if ((t & 31) == 0) red[t >> 5] = s;
    __syncthreads();
    s = red[0] + red[1] + red[2] + red[3];
    X[row * NP + t] = e / s;
}

// ---------------- final scatter-broadcast of the 576 unique rows --------------
__global__ __launch_bounds__(256)
void scatter_kernel(float4* __restrict__ out) {
    const int wq = threadIdx.x >> 6;          // 0..3
    const int dq = threadIdx.x & 63;          // 0..63
    const int w  = blockIdx.x * 4 + wq;
    const int h  = blockIdx.y;
    const int b  = blockIdx.z;
    const int uh = h / 5;
    const int uw = (w * 24) / 160;
    const float4* src = reinterpret_cast<const float4*>(g_U)
                        + (long)((b * S_) + uh * T_ + uw) * (DIM / 4);
    float4* dst = out + (long)(((b * H_) + h) * W_ + w) * (DIM / 4);
    dst[dq] = src[dq];
}

// ==============================================================================
extern "C" void kernel_launch(void* const* d_in, const int* in_sizes, int n_in,
                              void* d_out, int out_size) {
    const float* token_init  = (const float*)d_in[0];
    const float* point_token = (const float*)d_in[1];
    const float* nr_w1 = (const float*)d_in[2];
    const float* nr_b1 = (const float*)d_in[3];
    const float* nr_w2 = (const float*)d_in[4];
    const float* nr_b2 = (const float*)d_in[5];
    const float* na_w1 = (const float*)d_in[6];
    const float* na_b1 = (const float*)d_in[7];
    const float* na_w2 = (const float*)d_in[8];
    const float* na_b2 = (const float*)d_in[9];
    const float* tf_w1 = (const float*)d_in[10];
    const float* tf_b1 = (const float*)d_in[11];
    const float* tf_w2 = (const float*)d_in[12];
    const float* tf_b2 = (const float*)d_in[13];
    float* out = (float*)d_out;

    float *t_p, *A0_p, *H_p, *adj_p, *attn_p, *fus_p, *U_p;
    cudaGetSymbolAddress((void**)&t_p,    g_t);
    cudaGetSymbolAddress((void**)&A0_p,   g_A0);
    cudaGetSymbolAddress((void**)&H_p,    g_H);
    cudaGetSymbolAddress((void**)&adj_p,  g_adj);
    cudaGetSymbolAddress((void**)&attn_p, g_attn);
    cudaGetSymbolAddress((void**)&fus_p,  g_fus);
    cudaGetSymbolAddress((void**)&U_p,    g_U);

    const float scale = 0.0625f;               // dim^-0.5
    const float rs = 0.20412414523193154f;     // 24^-0.5

    // 1. template tokens
    build_t_kernel<<<dim3(S_, B_), 256>>>(token_init);

    // 2. A0 = t @ P^T * scale  [4,576,128]
    gemm_tc<true, false, false, false, false><<<dim3(NP/BN, S_/BM, B_), 256>>>(
        t_p, point_token, nullptr, nullptr, nullptr, nullptr, A0_p, nullptr,
        DIM, scale,
        (long)S_*DIM, DIM, 0,
        (long)NP*DIM, DIM,
        (long)S_*NP, NP, 0, 0);

    // 3. fc1 (nr & na merged): H = gelu(A0 @ w1 + b1)   [4,576,1024]
    gemm_tc<false, true, true, false, true><<<dim3(HID/BN, S_/BM, 2*B_), 256>>>(
        A0_p, nr_w1, na_w1, nr_b1, na_b1, nullptr, H_p, H_p,
        NP, 1.f,
        (long)S_*NP, NP, 0,
        0, HID,
        (long)S_*2*HID, 2*HID, HID, 0);

    // 4. fc2 (nr & na merged): adj / attn = H @ w2 + b2
    gemm_tc<false, false, true, false, true><<<dim3(NP/BN, S_/BM, 2*B_), 256>>>(
        H_p, nr_w2, na_w2, nr_b2, na_b2, nullptr, adj_p, attn_p,
        HID, 1.f,
        (long)S_*2*HID, 2*HID, HID,
        0, NP,
        (long)S_*NP, NP, 0, 0);

    // 5. node_w / node_h -> token_n
    node_wh_kernel<<<dim3(T_, B_, 2), 256>>>(rs);

    // 6. token_fused MLP over the 48-axis -> [4,128,256]
    token_fused_kernel<<<dim3(B_ * NP), 128>>>(tf_w1, tf_b1, tf_w2, tf_b2);

    // 7. softmax over the 128 points
    softmax128_kernel<<<dim3(B_ * S_), 128>>>(attn_p);

    // 8. U = attn @ token_fused + t   [4,576,256]
    gemm_tc<false, false, false, true, false><<<dim3(DIM/BN, S_/BM, B_), 256>>>(
        attn_p, fus_p, nullptr, nullptr, nullptr, t_p, U_p, nullptr,
        NP, 1.f,
        (long)S_*NP, NP, 0,
        (long)NP*DIM, DIM,
        (long)S_*DIM, DIM, 0, (long)S_*DIM);

    // 9. broadcast unique rows to the full [4,19200,256] output
    scatter_kernel<<<dim3(W_/4, H_, B_), 256>>>((float4*)out);
}

// round 4
// speedup vs baseline: 1.4805x; 1.4805x over previous
#include <cuda_runtime.h>
#include <math.h>
#include <stdint.h>

// Problem constants (shapes fixed by the dataset)
#define B_    4
#define S0    12          // token_init side; compact row count per batch = 144
#define M144  144         // unique rows per batch
#define MT    576         // B_*M144
#define DIM   256
#define NP    128         // nPnt
#define HID   512         // 4*nPnt
#define H_    120
#define W_    160

typedef unsigned long long ull;

// ---------------- scratch (device globals) ------------------------------------
__device__ float g_A0  [MT * NP];              // compact t @ P^T / 16   [576,128]
__device__ float g_H   [MT * 2 * HID];         // hidden, nr [0,512) na [512,1024)
__device__ float g_adj [MT * NP];              // node_adj  [576,128]
__device__ float g_attn[MT * NP];              // softmax in-place [576,128]
__device__ float g_nod [B_ * 24 * NP * DIM];   // compact token_n [4,24,128,256]
__device__ float g_fus [B_ * NP * DIM];        // token_fused [4,128,256]
__device__ float g_U   [MT * DIM];             // unique output rows [576,256]

__device__ __forceinline__ float gelu_exact(float x) {
    return 0.5f * x * (1.0f + erff(x * 0.70710678118654752440f));
}
__device__ __forceinline__ ull pack2(float x, float y) {
    ull r; asm("mov.b64 %0, {%1, %2};" : "=l"(r) : "f"(x), "f"(y)); return r;
}
__device__ __forceinline__ void unpack2(ull v, float& x, float& y) {
    asm("mov.b64 {%0, %1}, %2;" : "=f"(x), "=f"(y) : "l"(v));
}
__device__ __forceinline__ ull fma2(ull a, ull b, ull c) {
    ull d; asm("fma.rn.f32x2 %0, %1, %2, %3;" : "=l"(d) : "l"(a), "l"(b), "l"(c));
    return d;
}

// ===================== templated fp32 GEMM ====================================
// C = act( alpha * A @ B(^T) + bias ) + R
// DUAL: blockIdx.z = bz*2+br; br selects B0/B1, bias0/bias1, C0/C1, ofsA/ofsC.
template<int BM, int BN, int BK, int TM, int TN,
         bool TRANSB, bool ACT, bool BIAS, bool RESID, bool DUAL>
__global__ __launch_bounds__((BM / TM) * (BN / TN))
void gemm_f32(const float* __restrict__ A,
              const float* __restrict__ B0, const float* __restrict__ B1,
              const float* __restrict__ bias0, const float* __restrict__ bias1,
              const float* __restrict__ R,
              float* __restrict__ C0, float* __restrict__ C1,
              int K, float alpha,
              long sA, int lda, int ofsA,
              long sB, int ldb,
              long sC, int ldc, int ofsC,
              long sR, int ldr)
{
    constexpr int THREADS = (BM / TM) * (BN / TN);
    constexpr int NA = (BM * BK) / THREADS;     // A elems per thread per tile
    constexpr int NB = (BN * BK) / THREADS;     // B elems per thread per tile
    static_assert(NA * THREADS == BM * BK, "A load divisibility");
    static_assert(NB * THREADS == BN * BK, "B load divisibility");

    const int z  = blockIdx.z;
    const int bz = DUAL ? (z >> 1) : z;
    const int br = DUAL ? (z & 1) : 0;

    const float* Bw  = (DUAL && br) ? B1 : B0;
    const float* bia = (DUAL && br) ? bias1 : bias0;
    float*       C   = (DUAL && br) ? C1 : C0;

    A  += (long)bz * sA + (long)br * ofsA;
    Bw += (long)bz * sB;
    C  += (long)bz * sC + (long)br * ofsC;
    const float* Rp = R + (long)bz * sR;

    __shared__ float As[BK][BM + 1];
    __shared__ float Bs[BK][BN + 1];

    const int tid  = threadIdx.x;
    const int row0 = blockIdx.y * BM;
    const int col0 = blockIdx.x * BN;
    const int tn   = tid % (BN / TN);
    const int tm   = tid / (BN / TN);
    const int m0   = tm * TM;
    const int n0   = tn * TN;

    float acc[TM][TN];
#pragma unroll
    for (int i = 0; i < TM; i++)
#pragma unroll
        for (int j = 0; j < TN; j++) acc[i][j] = 0.f;

    float regA[NA], regB[NB];
    const int nT = K / BK;

    // prologue: load tile 0 into regs
#pragma unroll
    for (int j = 0; j < NA; j++) {
        int idx = tid + j * THREADS;
        int r = idx / BK, k = idx % BK;
        regA[j] = A[(long)(row0 + r) * lda + k];
    }
#pragma unroll
    for (int j = 0; j < NB; j++) {
        int idx = tid + j * THREADS;
        if (TRANSB) { int n = idx / BK, k = idx % BK; regB[j] = Bw[(long)(col0 + n) * ldb + k]; }
        else        { int k = idx / BN, n = idx % BN; regB[j] = Bw[(long)k * ldb + col0 + n]; }
    }

    for (int t = 0; t < nT; t++) {
        // regs -> smem
#pragma unroll
        for (int j = 0; j < NA; j++) {
            int idx = tid + j * THREADS;
            int r = idx / BK, k = idx % BK;
            As[k][r] = regA[j];
        }
#pragma unroll
        for (int j = 0; j < NB; j++) {
            int idx = tid + j * THREADS;
            if (TRANSB) { int n = idx / BK, k = idx % BK; Bs[k][n] = regB[j]; }
            else        { int k = idx / BN, n = idx % BN; Bs[k][n] = regB[j]; }
        }
        __syncthreads();

        // prefetch next tile
        if (t + 1 < nT) {
            const int k0 = (t + 1) * BK;
#pragma unroll
            for (int j = 0; j < NA; j++) {
                int idx = tid + j * THREADS;
                int r = idx / BK, k = idx % BK;
                regA[j] = A[(long)(row0 + r) * lda + k0 + k];
            }
#pragma unroll
            for (int j = 0; j < NB; j++) {
                int idx = tid + j * THREADS;
                if (TRANSB) { int n = idx / BK, k = idx % BK; regB[j] = Bw[(long)(col0 + n) * ldb + k0 + k]; }
                else        { int k = idx / BN, n = idx % BN; regB[j] = Bw[(long)(k0 + k) * ldb + col0 + n]; }
            }
        }

        // compute
#pragma unroll
        for (int kk = 0; kk < BK; kk++) {
            float av[TM], bv[TN];
#pragma unroll
            for (int i = 0; i < TM; i++) av[i] = As[kk][m0 + i];
#pragma unroll
            for (int j = 0; j < TN; j++) bv[j] = Bs[kk][n0 + j];
#pragma unroll
            for (int i = 0; i < TM; i++)
#pragma unroll
                for (int j = 0; j < TN; j++)
                    acc[i][j] += av[i] * bv[j];
        }
        __syncthreads();
    }

    // epilogue
    float bf[TN];
#pragma unroll
    for (int j = 0; j < TN; j++) bf[j] = BIAS ? bia[col0 + n0 + j] : 0.f;
#pragma unroll
    for (int i = 0; i < TM; i++) {
        const int row = row0 + m0 + i;
#pragma unroll
        for (int j = 0; j < TN; j++) {
            float v = acc[i][j] * alpha + bf[j];
            if (ACT)   v = gelu_exact(v);
            if (RESID) v += Rp[(long)row * ldr + col0 + n0 + j];
            C[(long)row * ldc + col0 + n0 + j] = v;
        }
    }
}

// ---------------- node_w / node_h on the compact 12x12 grid -------------------
// mode 0: srow=h'      : 2 * sum_{w'} adj[h',w',p] * t[h',w',d] * rs
// mode 1: srow=12+w'   : 2 * sum_{h'} adj[h',w',p] * t[h',w',d] * rs
__global__ __launch_bounds__(256)
void node_wh_kernel(const float* __restrict__ token_init, float rs2) {
    __shared__ __align__(16) float adj_s[S0][NP];     // 6 KB
    __shared__ __align__(16) float t_s  [S0][DIM];    // 12 KB
    const int fix  = blockIdx.x;   // 0..11
    const int b    = blockIdx.y;
    const int mode = blockIdx.z;
    const int tid  = threadIdx.x;

    for (int idx = tid; idx < S0 * NP; idx += 256) {
        int m = idx >> 7, p = idx & 127;
        int r = mode ? (m * S0 + fix) : (fix * S0 + m);
        adj_s[m][p] = g_adj[(b * M144 + r) * NP + p];
    }
    for (int idx = tid; idx < S0 * DIM; idx += 256) {
        int m = idx >> 8, d = idx & 255;
        int r = mode ? (m * S0 + fix) : (fix * S0 + m);
        t_s[m][d] = token_init[((long)b * M144 + r) * DIM + d];
    }
    __syncthreads();

    const int d = tid;
    const int srow = mode ? (S0 + fix) : fix;
#pragma unroll
    for (int pb = 0; pb < 8; pb++) {
        ull acc2[8];
#pragma unroll
        for (int i = 0; i < 8; i++) acc2[i] = pack2(0.f, 0.f);
#pragma unroll
        for (int m = 0; m < S0; m++) {
            float tv = t_s[m][d];
            ull tv2 = pack2(tv, tv);
            const ull* ap = (const ull*)&adj_s[m][pb * 16];
#pragma unroll
            for (int i = 0; i < 8; i++)
                acc2[i] = fma2(ap[i], tv2, acc2[i]);
        }
#pragma unroll
        for (int i = 0; i < 8; i++) {
            float x, y; unpack2(acc2[i], x, y);
            g_nod[((long)(b * 24 + srow) * NP + pb * 16 + 2 * i + 0) * DIM + d] = x * rs2;
            g_nod[((long)(b * 24 + srow) * NP + pb * 16 + 2 * i + 1) * DIM + d] = y * rs2;
        }
    }
}

// ---------------- token_fused MLP, folded 48->24 axis, 2 d's per thread -------
__global__ __launch_bounds__(128)
void token_fused_kernel(const float* __restrict__ w1, const float* __restrict__ b1,
                        const float* __restrict__ w2, const float* __restrict__ b2) {
    __shared__ float w1t[48][24];   // folded+transposed: w1t[j][i] = w1[2i][j]+w1[2i+1][j]
    __shared__ float b1s[48];
    __shared__ float w2s[48];
    const int tid = threadIdx.x;
    for (int idx = tid; idx < 48 * 24; idx += 128) {
        int j = idx / 24, i = idx % 24;
        w1t[j][i] = w1[(2 * i) * 48 + j] + w1[(2 * i + 1) * 48 + j];
    }
    if (tid < 48) { b1s[tid] = b1[tid]; w2s[tid] = w2[tid]; }
    __syncthreads();

    const int bp = blockIdx.x;        // 0..511 = b*128+p
    const int b  = bp >> 7;
    const int p  = bp & 127;
    const int d  = tid * 2;

    float xa[24], xb[24];
#pragma unroll
    for (int i = 0; i < 24; i++) {
        float2 v = *(const float2*)&g_nod[((long)(b * 24 + i) * NP + p) * DIM + d];
        xa[i] = v.x; xb[i] = v.y;
    }

    float outa = b2[0], outb = b2[0];
    for (int j = 0; j < 48; j++) {
        float a0 = b1s[j], a1 = b1s[j];
        const float4* wr = (const float4*)&w1t[j][0];
#pragma unroll
        for (int i4 = 0; i4 < 6; i4++) {
            float4 wv = wr[i4];
            a0 += xa[i4 * 4 + 0] * wv.x + xa[i4 * 4 + 1] * wv.y
                + xa[i4 * 4 + 2] * wv.z + xa[i4 * 4 + 3] * wv.w;
            a1 += xb[i4 * 4 + 0] * wv.x + xb[i4 * 4 + 1] * wv.y
                + xb[i4 * 4 + 2] * wv.z + xb[i4 * 4 + 3] * wv.w;
        }
        float w2v = w2s[j];
        outa += gelu_exact(a0) * w2v;
        outb += gelu_exact(a1) * w2v;
    }
    *(float2*)&g_fus[bp * DIM + d] = make_float2(outa, outb);
}

// ---------------- row softmax, N = 128, one block per row ---------------------
__global__ __launch_bounds__(128)
void softmax128_kernel(float* __restrict__ X) {
    const int row = blockIdx.x;
    const int t = threadIdx.x;
    float v = X[row * NP + t];
    __shared__ float red[4];
    float m = v;
#pragma unroll
    for (int o = 16; o; o >>= 1) m = fmaxf(m, __shfl_xor_sync(0xffffffffu, m, o));
    if ((t & 31) == 0) red[t >> 5] = m;
    __syncthreads();
    m = fmaxf(fmaxf(red[0], red[1]), fmaxf(red[2], red[3]));
    float e = expf(v - m);
    __syncthreads();
    float s = e;
#pragma unroll
    for (int o = 16; o; o >>= 1) s += __shfl_xor_sync(0xffffffffu, s, o);
    if ((t & 31) == 0) red[t >> 5] = s;
    __syncthreads();
    s = red[0] + red[1] + red[2] + red[3];
    X[row * NP + t] = e / s;
}

// ---------------- final scatter-broadcast of the 144 unique rows --------------
__global__ __launch_bounds__(256)
void scatter_kernel(float4* __restrict__ out) {
    const int wq = threadIdx.x >> 6;          // 0..3
    const int dq = threadIdx.x & 63;          // 0..63
    const int w  = blockIdx.x * 4 + wq;
    const int h  = blockIdx.y;
    const int b  = blockIdx.z;
    const int r  = (h / 10) * S0 + (3 * w) / 40;
    const float4* src = reinterpret_cast<const float4*>(g_U)
                        + (long)(b * M144 + r) * (DIM / 4);
    float4* dst = out + (long)(((b * H_) + h) * W_ + w) * (DIM / 4);
    dst[dq] = src[dq];
}

// ==============================================================================
extern "C" void kernel_launch(void* const* d_in, const int* in_sizes, int n_in,
                              void* d_out, int out_size) {
    const float* token_init  = (const float*)d_in[0];   // [4,12,12,256] == compact t
    const float* point_token = (const float*)d_in[1];
    const float* nr_w1 = (const float*)d_in[2];
    const float* nr_b1 = (const float*)d_in[3];
    const float* nr_w2 = (const float*)d_in[4];
    const float* nr_b2 = (const float*)d_in[5];
    const float* na_w1 = (const float*)d_in[6];
    const float* na_b1 = (const float*)d_in[7];
    const float* na_w2 = (const float*)d_in[8];
    const float* na_b2 = (const float*)d_in[9];
    const float* tf_w1 = (const float*)d_in[10];
    const float* tf_b1 = (const float*)d_in[11];
    const float* tf_w2 = (const float*)d_in[12];
    const float* tf_b2 = (const float*)d_in[13];
    float* out = (float*)d_out;

    float *A0_p, *H_p, *adj_p, *attn_p, *fus_p, *U_p;
    cudaGetSymbolAddress((void**)&A0_p,   g_A0);
    cudaGetSymbolAddress((void**)&H_p,    g_H);
    cudaGetSymbolAddress((void**)&adj_p,  g_adj);
    cudaGetSymbolAddress((void**)&attn_p, g_attn);
    cudaGetSymbolAddress((void**)&fus_p,  g_fus);
    cudaGetSymbolAddress((void**)&U_p,    g_U);

    const float scale = 0.0625f;                    // dim^-0.5
    const float rs2   = 2.f * 0.20412414523193154f; // 2 * 24^-0.5

    // 1. A0 = t144 @ P^T * scale   [4*144,128]  (t144 == token_init)
    gemm_f32<16, 32, 16, 2, 4, true, false, false, false, false>
        <<<dim3(NP / 32, M144 / 16, B_), 64>>>(
        token_init, point_token, nullptr, nullptr, nullptr, nullptr, A0_p, nullptr,
        DIM, scale,
        (long)M144 * DIM, DIM, 0,
        (long)NP * DIM, DIM,
        (long)M144 * NP, NP, 0,
        0, 0);

    // 2. fc1 (nr & na): H = gelu(A0 @ w1 + b1)   [576,1024]
    gemm_f32<32, 64, 16, 4, 4, false, true, true, false, true>
        <<<dim3(HID / 64, MT / 32, 2), 128>>>(
        A0_p, nr_w1, na_w1, nr_b1, na_b1, nullptr, H_p, H_p,
        NP, 1.f,
        0, NP, 0,
        0, HID,
        0, 2 * HID, HID,
        0, 0);

    // 3. fc2 (nr & na): adj / attn = H @ w2 + b2   [576,128] each
    gemm_f32<32, 32, 16, 4, 2, false, false, true, false, true>
        <<<dim3(NP / 32, MT / 32, 2), 128>>>(
        H_p, nr_w2, na_w2, nr_b2, na_b2, nullptr, adj_p, attn_p,
        HID, 1.f,
        0, 2 * HID, HID,
        0, NP,
        0, NP, 0,
        0, 0);

    // 4. node_w / node_h on 12x12 -> compact token_n [4,24,128,256]
    node_wh_kernel<<<dim3(S0, B_, 2), 256>>>(token_init, rs2);

    // 5. token_fused MLP (folded 24-axis) -> [4,128,256]
    token_fused_kernel<<<dim3(B_ * NP), 128>>>(tf_w1, tf_b1, tf_w2, tf_b2);

    // 6. softmax over the 128 points (576 compact rows)
    softmax128_kernel<<<dim3(MT), 128>>>(attn_p);

    // 7. U = attn @ token_fused + t144   [4*144,256]
    gemm_f32<16, 64, 16, 2, 4, false, false, false, true, false>
        <<<dim3(DIM / 64, M144 / 16, B_), 128>>>(
        attn_p, fus_p, nullptr, nullptr, nullptr, token_init, U_p, nullptr,
        NP, 1.f,
        (long)M144 * NP, NP, 0,
        (long)NP * DIM, DIM,
        (long)M144 * DIM, DIM, 0,
        (long)M144 * DIM, DIM);

    // 8. broadcast unique rows to the full [4,19200,256] output
    scatter_kernel<<<dim3(W_ / 4, H_, B_), 256>>>((float4*)out);
}